// round 2
// baseline (speedup 1.0000x reference)
#include <cuda_runtime.h>
#include <math.h>

#define BB 16
#define CC 128
#define JL 16
#define NBCODE 16384
#define NTOT 5456
#define FHN (BB*CC*JL*JL)   // 524288
#define NSPLIT 8
#define CODES_PER_SPLIT (NBCODE/NSPLIT)  // 2048

// ---- device scratch (no allocations allowed) ----
__device__ float g_frest[FHN];
__device__ float g_rnc[4096*CC];
__device__ float g_r2[4096];
__device__ float g_hs[FHN];
__device__ unsigned long long g_part[NSPLIT*4096];
__device__ int   g_idx[4096];
__device__ int   g_counts[NBCODE];
__device__ float g_loss;
__device__ float g_esq[NBCODE];

// ------------------------------------------------------------------
__global__ void init_kernel(const float* __restrict__ f, float* __restrict__ fhat) {
    int i = blockIdx.x * blockDim.x + threadIdx.x;
    if (i < FHN) { fhat[i] = 0.0f; g_frest[i] = f[i]; }
    if (i < NBCODE) g_counts[i] = 0;
    if (i == 0) g_loss = 0.0f;
}

__global__ void esq_kernel(const float* __restrict__ emb) {
    int k = blockIdx.x * blockDim.x + threadIdx.x;
    if (k >= NBCODE) return;
    const float* e = emb + (size_t)k * CC;
    float s = 0.0f;
#pragma unroll 8
    for (int d = 0; d < CC; d++) s = fmaf(e[d], e[d], s);
    g_esq[k] = s;
}

// area pooling: f_rest [B,C,16,16] -> r_nc [N, C], n = (b*sn + s)*sn + t
__global__ void pool_kernel(int sn, int fct) {
    int i = blockIdx.x * blockDim.x + threadIdx.x;
    int N = BB * sn * sn;
    if (i >= N * CC) return;
    int n = i / CC, c = i % CC;
    int t = n % sn;
    int s = (n / sn) % sn;
    int b = n / (sn * sn);
    const float* base = g_frest + ((size_t)(b * CC + c)) * (JL * JL);
    float acc = 0.0f;
    for (int dj = 0; dj < fct; dj++)
        for (int dl = 0; dl < fct; dl++)
            acc += base[(s * fct + dj) * JL + (t * fct + dl)];
    g_rnc[n * CC + c] = acc * (1.0f / (float)(fct * fct));
}

// per-row squared norm, sequential fp32 (matches reference magnitude/rounding regime)
__global__ void r2_kernel(int N) {
    int n = blockIdx.x * blockDim.x + threadIdx.x;
    if (n >= N) return;
    const float* r = g_rnc + (size_t)n * CC;
    float s = 0.0f;
#pragma unroll 8
    for (int d = 0; d < CC; d++) s = fmaf(r[d], r[d], s);
    g_r2[n] = s;
}

// scoring + per-split argmin: 16 rows per block, 2048 codes per split.
// CRITICAL: distance is computed as round(round(r2 + e_sq) - 2*dot), matching the
// reference's |r|^2-dominated rounding so near-ties resolve identically
// (tie-break by lowest index via the u64 key).
__global__ void argmin_kernel(const float* __restrict__ emb, int N) {
    __shared__ float4 sr4[16][CC/4];
    __shared__ float sr2[16];
    __shared__ unsigned long long sbest[16];
    int row0 = blockIdx.x * 16;
    int tid  = threadIdx.x;

    float* srf = (float*)sr4;
    for (int i = tid; i < 16 * CC; i += 256) {
        int m = i >> 7, d = i & 127;
        srf[m * CC + d] = g_rnc[(row0 + m) * CC + d];
    }
    if (tid < 16) { sbest[tid] = ~0ULL; sr2[tid] = g_r2[row0 + tid]; }
    __syncthreads();

    float bd[16];
    int   bi[16];
#pragma unroll
    for (int m = 0; m < 16; m++) { bd[m] = 3.4e38f; bi[m] = 0; }

    int k0 = blockIdx.y * CODES_PER_SPLIT;
    for (int kk = 0; kk < CODES_PER_SPLIT; kk += 256) {
        int k = k0 + kk + tid;
        const float4* e4 = (const float4*)(emb + (size_t)k * CC);
        float acc[16];
#pragma unroll
        for (int m = 0; m < 16; m++) acc[m] = 0.0f;
#pragma unroll
        for (int d = 0; d < CC/4; d++) {
            float4 e = e4[d];
#pragma unroll
            for (int m = 0; m < 16; m++) {
                float4 r = sr4[m][d];
                acc[m] += e.x*r.x + e.y*r.y + e.z*r.z + e.w*r.w;
            }
        }
        float es = g_esq[k];
#pragma unroll
        for (int m = 0; m < 16; m++) {
            float t  = __fadd_rn(sr2[m], es);          // round(r2 + e_sq)
            float sc = __fsub_rn(t, 2.0f * acc[m]);    // round(t - 2*dot), 2*dot exact
            if (sc < bd[m]) { bd[m] = sc; bi[m] = k; }
        }
    }
#pragma unroll
    for (int m = 0; m < 16; m++) {
        unsigned u = __float_as_uint(bd[m]);
        u = (u & 0x80000000u) ? ~u : (u | 0x80000000u);
        unsigned long long key = ((unsigned long long)u << 32) | (unsigned)bi[m];
        atomicMin(&sbest[m], key);
    }
    __syncthreads();
    if (tid < 16) g_part[blockIdx.y * 4096 + row0 + tid] = sbest[tid];
}

__global__ void argmin_reduce(int N) {
    int n = blockIdx.x * blockDim.x + threadIdx.x;
    if (n >= N) return;
    unsigned long long best = ~0ULL;
#pragma unroll
    for (int s = 0; s < NSPLIT; s++) {
        unsigned long long v = g_part[s * 4096 + n];
        if (v < best) best = v;
    }
    int idx = (int)(best & 0xFFFFFFFFULL);
    g_idx[n] = idx;
    atomicAdd(&g_counts[idx], 1);
}

__device__ __forceinline__ float cubicw(float x) {
    const float a = -0.75f;
    float ax = fabsf(x);
    if (ax <= 1.0f) return ((a + 2.0f) * ax - (a + 3.0f)) * ax * ax + 1.0f;
    if (ax < 2.0f)  return a * (((ax - 5.0f) * ax + 8.0f) * ax - 4.0f);
    return 0.0f;
}

// gather + bicubic upsample to [B,C,16,16]; exact identity at sn=16
__global__ void upsample_kernel(const float* __restrict__ emb, int sn) {
    int i = blockIdx.x * blockDim.x + threadIdx.x;
    if (i >= FHN) return;
    int l = i & 15;
    int j = (i >> 4) & 15;
    int c = (i >> 8) & 127;
    int b = i >> 15;
    float scale = (float)sn / 16.0f;
    float xj = (j + 0.5f) * scale - 0.5f;
    int x0j = (int)floorf(xj);
    float tj = xj - (float)x0j;
    float xl = (l + 0.5f) * scale - 0.5f;
    int x0l = (int)floorf(xl);
    float tl = xl - (float)x0l;

    float acc = 0.0f;
#pragma unroll
    for (int kj = 0; kj < 4; kj++) {
        float wj = cubicw(tj + 1.0f - (float)kj);
        int sj = min(max(x0j - 1 + kj, 0), sn - 1);
#pragma unroll
        for (int kl = 0; kl < 4; kl++) {
            float wl = cubicw(tl + 1.0f - (float)kl);
            int sl = min(max(x0l - 1 + kl, 0), sn - 1);
            int n = (b * sn + sj) * sn + sl;
            acc += wj * wl * emb[(size_t)g_idx[n] * CC + c];
        }
    }
    g_hs[i] = acc;
}

// conv3x3 (SAME) + bias, phi blend (0.5/0.5), f_hat/f_rest update, loss accumulation.
// One block per (b, group of 16 c_out); 256 threads = one per pixel.
__global__ void conv_phi_kernel(const float* __restrict__ w, const float* __restrict__ bias,
                                const float* __restrict__ f_in, float* __restrict__ fhat) {
    __shared__ float plane[256];
    __shared__ float wsh[16 * 9];
    __shared__ float red[256];

    int b    = blockIdx.x >> 3;
    int cog  = blockIdx.x & 7;
    int cbase = cog * 16;
    int tid  = threadIdx.x;
    int j = tid >> 4, l = tid & 15;

    float acc[16];
#pragma unroll
    for (int co = 0; co < 16; co++) acc[co] = bias[cbase + co];

    for (int ci = 0; ci < CC; ci++) {
        __syncthreads();
        plane[tid] = g_hs[((size_t)(b * CC + ci) << 8) + tid];
        if (tid < 144) {
            int co = tid / 9, q = tid % 9;
            wsh[tid] = w[((size_t)(cbase + co) * CC + ci) * 9 + q];
        }
        __syncthreads();
        float v[9];
#pragma unroll
        for (int dj = 0; dj < 3; dj++)
#pragma unroll
            for (int dl = 0; dl < 3; dl++) {
                int jj = j + dj - 1, ll = l + dl - 1;
                v[dj * 3 + dl] = (jj >= 0 && jj < 16 && ll >= 0 && ll < 16)
                                 ? plane[(jj << 4) + ll] : 0.0f;
            }
#pragma unroll
        for (int co = 0; co < 16; co++) {
            float s = 0.0f;
#pragma unroll
            for (int q = 0; q < 9; q++) s += wsh[co * 9 + q] * v[q];
            acc[co] += s;
        }
    }

    float lsum = 0.0f;
#pragma unroll
    for (int co = 0; co < 16; co++) {
        size_t gi = ((size_t)(b * CC + cbase + co) << 8) + tid;
        float h = 0.5f * g_hs[gi] + 0.5f * acc[co];
        float fh = fhat[gi] + h;
        fhat[gi] = fh;
        g_frest[gi] -= h;
        float d = fh - f_in[gi];
        lsum += d * d;
    }
    red[tid] = lsum;
    __syncthreads();
    for (int s = 128; s > 0; s >>= 1) {
        if (tid < s) red[tid] += red[tid + s];
        __syncthreads();
    }
    // loss = (1+beta)/SN * sum(mse) = 0.25 * sum(sum_sq)/FHN
    if (tid == 0) atomicAdd(&g_loss, red[0] * (0.25f / (float)FHN));
}

__global__ void final_kernel(float* __restrict__ out) {
    __shared__ float red[256];
    int tid = threadIdx.x;
    float s = 0.0f;
    for (int k = tid; k < NBCODE; k += 256) {
        float p = (float)g_counts[k] * (1.0f / (float)NTOT);
        s += p * logf(p + 1e-10f);
    }
    red[tid] = s;
    __syncthreads();
    for (int st = 128; st > 0; st >>= 1) {
        if (tid < st) red[tid] += red[tid + st];
        __syncthreads();
    }
    if (tid == 0) {
        out[FHN]     = g_loss;
        out[FHN + 1] = expf(-red[0]);
    }
}

// ------------------------------------------------------------------
extern "C" void kernel_launch(void* const* d_in, const int* in_sizes, int n_in,
                              void* d_out, int out_size) {
    const float* f     = (const float*)d_in[0];   // [16,128,16,16]
    const float* emb   = (const float*)d_in[1];   // [16384,128]
    const float* phi_w = (const float*)d_in[2];   // [4,128,128,3,3]
    const float* phi_b = (const float*)d_in[3];   // [4,128]
    float* out = (float*)d_out;                   // [524288 fhat | loss | perplexity]

    init_kernel<<<(FHN + 255) / 256, 256>>>(f, out);
    esq_kernel<<<NBCODE / 256, 256>>>(emb);

    const int sns[5]  = {1, 2, 4, 8, 16};
    const int phis[5] = {0, 1, 1, 2, 3};
    for (int si = 0; si < 5; si++) {
        int sn = sns[si];
        int N = BB * sn * sn;
        int fct = 16 / sn;
        pool_kernel<<<(N * CC + 255) / 256, 256>>>(sn, fct);
        r2_kernel<<<(N + 255) / 256, 256>>>(N);
        dim3 g((N + 15) / 16, NSPLIT);
        argmin_kernel<<<g, 256>>>(emb, N);
        argmin_reduce<<<(N + 255) / 256, 256>>>(N);
        upsample_kernel<<<FHN / 256, 256>>>(emb, sn);
        int k = phis[si];
        conv_phi_kernel<<<128, 256>>>(phi_w + (size_t)k * CC * CC * 9,
                                      phi_b + (size_t)k * CC, f, out);
    }
    final_kernel<<<1, 256>>>(out);
}

// round 3
// speedup vs baseline: 6.1059x; 6.1059x over previous
#include <cuda_runtime.h>
#include <math.h>

#define BB 16
#define CC 128
#define JL 16
#define NBCODE 16384
#define NTOT 5456
#define FHN (BB*CC*JL*JL)   // 524288
#define NSPLIT 8
#define CODES_PER_SPLIT (NBCODE/NSPLIT)  // 2048
#define TILE_K 128
#define ARGMIN_SMEM (TILE_K * 33 * (int)sizeof(float4))   // 67584 bytes

// ---- device scratch (no allocations allowed) ----
__device__ float g_frest[FHN];
__device__ float g_rnc[4096*CC];
__device__ float g_r2[4096];
__device__ float g_hs[FHN];
__device__ unsigned long long g_part[NSPLIT*4096];
__device__ int   g_idx[4096];
__device__ int   g_counts[NBCODE];
__device__ float g_loss;
__device__ float g_esq[NBCODE];

// ------------------------------------------------------------------
__global__ void init_kernel(const float* __restrict__ f, float* __restrict__ fhat) {
    int i = blockIdx.x * blockDim.x + threadIdx.x;
    if (i < FHN) { fhat[i] = 0.0f; g_frest[i] = f[i]; }
    if (i < NBCODE) g_counts[i] = 0;
    if (i == 0) g_loss = 0.0f;
}

__global__ void esq_kernel(const float* __restrict__ emb) {
    int k = blockIdx.x * blockDim.x + threadIdx.x;
    if (k >= NBCODE) return;
    const float* e = emb + (size_t)k * CC;
    float s = 0.0f;
#pragma unroll 8
    for (int d = 0; d < CC; d++) s = fmaf(e[d], e[d], s);
    g_esq[k] = s;
}

// area pooling: f_rest [B,C,16,16] -> r_nc [N, C], n = (b*sn + s)*sn + t
__global__ void pool_kernel(int sn, int fct) {
    int i = blockIdx.x * blockDim.x + threadIdx.x;
    int N = BB * sn * sn;
    if (i >= N * CC) return;
    int n = i / CC, c = i % CC;
    int t = n % sn;
    int s = (n / sn) % sn;
    int b = n / (sn * sn);
    const float* base = g_frest + ((size_t)(b * CC + c)) * (JL * JL);
    float acc = 0.0f;
    for (int dj = 0; dj < fct; dj++)
        for (int dl = 0; dl < fct; dl++)
            acc += base[(s * fct + dj) * JL + (t * fct + dl)];
    g_rnc[n * CC + c] = acc * (1.0f / (float)(fct * fct));
}

// per-row squared norm, sequential fp32 (matches reference magnitude/rounding regime)
__global__ void r2_kernel(int N) {
    int n = blockIdx.x * blockDim.x + threadIdx.x;
    if (n >= N) return;
    const float* r = g_rnc + (size_t)n * CC;
    float s = 0.0f;
#pragma unroll 8
    for (int d = 0; d < CC; d++) s = fmaf(r[d], r[d], s);
    g_r2[n] = s;
}

// scoring + per-split argmin: 16 rows per block, 2048 codes per split.
// emb staged through padded dynamic smem (coalesced LDG, conflict-free LDS).
// Each thread: one code of the 128-code tile x 8 rows.
// Distance is round(round(r2 + e_sq) - 2*dot) to match the reference's
// |r|^2-dominated fp32 rounding; ties resolve to lowest index via u64 key.
__global__ void argmin_kernel(const float* __restrict__ emb, int N) {
    extern __shared__ float4 se4[];          // [TILE_K][33] padded
    __shared__ float4 sr4[16][32];
    __shared__ float sr2[16];
    __shared__ unsigned long long sbest[16];

    int row0 = blockIdx.x * 16;
    int tid  = threadIdx.x;

    const float4* rnc4 = (const float4*)g_rnc;
    for (int i = tid; i < 16 * 32; i += 256) {
        int m = i >> 5, d = i & 31;
        sr4[m][d] = rnc4[(size_t)(row0 + m) * 32 + d];
    }
    if (tid < 16) { sbest[tid] = ~0ULL; sr2[tid] = g_r2[row0 + tid]; }

    int code  = tid & 127;   // code within tile
    int half  = tid >> 7;    // 0/1
    int rbase = half * 8;

    float bd[8]; int bi[8];
#pragma unroll
    for (int m = 0; m < 8; m++) { bd[m] = 3.4e38f; bi[m] = 0; }

    const float4* emb4 = (const float4*)emb;
    int k0s = blockIdx.y * CODES_PER_SPLIT;

    for (int tile = 0; tile < CODES_PER_SPLIT / TILE_K; tile++) {
        int k0 = k0s + tile * TILE_K;
        __syncthreads();
        // cooperative coalesced load: 128 codes x 32 float4
#pragma unroll
        for (int i = 0; i < 16; i++) {
            int j = tid + i * 256;
            int r = j >> 5, d = j & 31;
            se4[r * 33 + d] = emb4[(size_t)(k0 + r) * 32 + d];
        }
        __syncthreads();

        float acc[8];
#pragma unroll
        for (int m = 0; m < 8; m++) acc[m] = 0.0f;
        const float4* erow = se4 + code * 33;
#pragma unroll 8
        for (int d = 0; d < 32; d++) {
            float4 e = erow[d];
#pragma unroll
            for (int m = 0; m < 8; m++) {
                float4 r = sr4[rbase + m][d];
                acc[m] += e.x*r.x + e.y*r.y + e.z*r.z + e.w*r.w;
            }
        }
        float es = g_esq[k0 + code];
        int   k  = k0 + code;
#pragma unroll
        for (int m = 0; m < 8; m++) {
            float t  = __fadd_rn(sr2[rbase + m], es);       // round(r2 + e_sq)
            float sc = __fsub_rn(t, 2.0f * acc[m]);         // round(t - 2*dot)
            if (sc < bd[m]) { bd[m] = sc; bi[m] = k; }
        }
    }

#pragma unroll
    for (int m = 0; m < 8; m++) {
        unsigned u = __float_as_uint(bd[m]);
        u = (u & 0x80000000u) ? ~u : (u | 0x80000000u);
        unsigned long long key = ((unsigned long long)u << 32) | (unsigned)bi[m];
        atomicMin(&sbest[rbase + m], key);
    }
    __syncthreads();
    if (tid < 16) g_part[blockIdx.y * 4096 + row0 + tid] = sbest[tid];
}

__global__ void argmin_reduce(int N) {
    int n = blockIdx.x * blockDim.x + threadIdx.x;
    if (n >= N) return;
    unsigned long long best = ~0ULL;
#pragma unroll
    for (int s = 0; s < NSPLIT; s++) {
        unsigned long long v = g_part[s * 4096 + n];
        if (v < best) best = v;
    }
    int idx = (int)(best & 0xFFFFFFFFULL);
    g_idx[n] = idx;
    atomicAdd(&g_counts[idx], 1);
}

__device__ __forceinline__ float cubicw(float x) {
    const float a = -0.75f;
    float ax = fabsf(x);
    if (ax <= 1.0f) return ((a + 2.0f) * ax - (a + 3.0f)) * ax * ax + 1.0f;
    if (ax < 2.0f)  return a * (((ax - 5.0f) * ax + 8.0f) * ax - 4.0f);
    return 0.0f;
}

// gather + bicubic upsample to [B,C,16,16]; exact identity at sn=16
__global__ void upsample_kernel(const float* __restrict__ emb, int sn) {
    int i = blockIdx.x * blockDim.x + threadIdx.x;
    if (i >= FHN) return;
    int l = i & 15;
    int j = (i >> 4) & 15;
    int c = (i >> 8) & 127;
    int b = i >> 15;
    float scale = (float)sn / 16.0f;
    float xj = (j + 0.5f) * scale - 0.5f;
    int x0j = (int)floorf(xj);
    float tj = xj - (float)x0j;
    float xl = (l + 0.5f) * scale - 0.5f;
    int x0l = (int)floorf(xl);
    float tl = xl - (float)x0l;

    float acc = 0.0f;
#pragma unroll
    for (int kj = 0; kj < 4; kj++) {
        float wj = cubicw(tj + 1.0f - (float)kj);
        int sj = min(max(x0j - 1 + kj, 0), sn - 1);
#pragma unroll
        for (int kl = 0; kl < 4; kl++) {
            float wl = cubicw(tl + 1.0f - (float)kl);
            int sl = min(max(x0l - 1 + kl, 0), sn - 1);
            int n = (b * sn + sj) * sn + sl;
            acc += wj * wl * emb[(size_t)g_idx[n] * CC + c];
        }
    }
    g_hs[i] = acc;
}

// conv3x3 (SAME) + bias, phi blend (0.5/0.5), f_hat/f_rest update, loss accumulation.
__global__ void conv_phi_kernel(const float* __restrict__ w, const float* __restrict__ bias,
                                const float* __restrict__ f_in, float* __restrict__ fhat) {
    __shared__ float plane[256];
    __shared__ float wsh[16 * 9];
    __shared__ float red[256];

    int b    = blockIdx.x >> 3;
    int cog  = blockIdx.x & 7;
    int cbase = cog * 16;
    int tid  = threadIdx.x;
    int j = tid >> 4, l = tid & 15;

    float acc[16];
#pragma unroll
    for (int co = 0; co < 16; co++) acc[co] = bias[cbase + co];

    for (int ci = 0; ci < CC; ci++) {
        __syncthreads();
        plane[tid] = g_hs[((size_t)(b * CC + ci) << 8) + tid];
        if (tid < 144) {
            int co = tid / 9, q = tid % 9;
            wsh[tid] = w[((size_t)(cbase + co) * CC + ci) * 9 + q];
        }
        __syncthreads();
        float v[9];
#pragma unroll
        for (int dj = 0; dj < 3; dj++)
#pragma unroll
            for (int dl = 0; dl < 3; dl++) {
                int jj = j + dj - 1, ll = l + dl - 1;
                v[dj * 3 + dl] = (jj >= 0 && jj < 16 && ll >= 0 && ll < 16)
                                 ? plane[(jj << 4) + ll] : 0.0f;
            }
#pragma unroll
        for (int co = 0; co < 16; co++) {
            float s = 0.0f;
#pragma unroll
            for (int q = 0; q < 9; q++) s += wsh[co * 9 + q] * v[q];
            acc[co] += s;
        }
    }

    float lsum = 0.0f;
#pragma unroll
    for (int co = 0; co < 16; co++) {
        size_t gi = ((size_t)(b * CC + cbase + co) << 8) + tid;
        float h = 0.5f * g_hs[gi] + 0.5f * acc[co];
        float fh = fhat[gi] + h;
        fhat[gi] = fh;
        g_frest[gi] -= h;
        float d = fh - f_in[gi];
        lsum += d * d;
    }
    red[tid] = lsum;
    __syncthreads();
    for (int s = 128; s > 0; s >>= 1) {
        if (tid < s) red[tid] += red[tid + s];
        __syncthreads();
    }
    // loss = (1+beta)/SN * sum(mse) = 0.25 * sum(sum_sq)/FHN
    if (tid == 0) atomicAdd(&g_loss, red[0] * (0.25f / (float)FHN));
}

__global__ void final_kernel(float* __restrict__ out) {
    __shared__ float red[256];
    int tid = threadIdx.x;
    float s = 0.0f;
    for (int k = tid; k < NBCODE; k += 256) {
        float p = (float)g_counts[k] * (1.0f / (float)NTOT);
        s += p * logf(p + 1e-10f);
    }
    red[tid] = s;
    __syncthreads();
    for (int st = 128; st > 0; st >>= 1) {
        if (tid < st) red[tid] += red[tid + st];
        __syncthreads();
    }
    if (tid == 0) {
        out[FHN]     = g_loss;
        out[FHN + 1] = expf(-red[0]);
    }
}

// ------------------------------------------------------------------
extern "C" void kernel_launch(void* const* d_in, const int* in_sizes, int n_in,
                              void* d_out, int out_size) {
    const float* f     = (const float*)d_in[0];   // [16,128,16,16]
    const float* emb   = (const float*)d_in[1];   // [16384,128]
    const float* phi_w = (const float*)d_in[2];   // [4,128,128,3,3]
    const float* phi_b = (const float*)d_in[3];   // [4,128]
    float* out = (float*)d_out;                   // [524288 fhat | loss | perplexity]

    cudaFuncSetAttribute(argmin_kernel,
                         cudaFuncAttributeMaxDynamicSharedMemorySize, ARGMIN_SMEM);

    init_kernel<<<(FHN + 255) / 256, 256>>>(f, out);
    esq_kernel<<<NBCODE / 256, 256>>>(emb);

    const int sns[5]  = {1, 2, 4, 8, 16};
    const int phis[5] = {0, 1, 1, 2, 3};
    for (int si = 0; si < 5; si++) {
        int sn = sns[si];
        int N = BB * sn * sn;
        int fct = 16 / sn;
        pool_kernel<<<(N * CC + 255) / 256, 256>>>(sn, fct);
        r2_kernel<<<(N + 255) / 256, 256>>>(N);
        dim3 g((N + 15) / 16, NSPLIT);
        argmin_kernel<<<g, 256, ARGMIN_SMEM>>>(emb, N);
        argmin_reduce<<<(N + 255) / 256, 256>>>(N);
        upsample_kernel<<<FHN / 256, 256>>>(emb, sn);
        int k = phis[si];
        conv_phi_kernel<<<128, 256>>>(phi_w + (size_t)k * CC * CC * 9,
                                      phi_b + (size_t)k * CC, f, out);
    }
    final_kernel<<<1, 256>>>(out);
}

// round 4
// speedup vs baseline: 8.4679x; 1.3868x over previous
#include <cuda_runtime.h>
#include <math.h>

#define BB 16
#define CC 128
#define JL 16
#define NBCODE 16384
#define NTOT 5456
#define FHN (BB*CC*JL*JL)   // 524288
#define TILE_CODES 128
#define ROWS_PB 64
#define ARGMIN_DYN_SMEM (TILE_CODES * 33 * (int)sizeof(float4))   // 67584 bytes

// ---- device scratch (no allocations allowed) ----
__device__ float g_frest[FHN];
__device__ float g_rnc[4096*CC];
__device__ float g_r2[4096];
__device__ float g_hs[FHN];
__device__ unsigned long long g_part[32768];
__device__ int   g_idx[4096];
__device__ int   g_counts[NBCODE];
__device__ float g_loss;
__device__ float g_esq[NBCODE];

// ------------------------------------------------------------------
__global__ void init_kernel(const float* __restrict__ f, float* __restrict__ fhat) {
    int i = blockIdx.x * blockDim.x + threadIdx.x;
    if (i < FHN) { fhat[i] = 0.0f; g_frest[i] = f[i]; }
    if (i < NBCODE) g_counts[i] = 0;
    if (i == 0) g_loss = 0.0f;
}

__global__ void esq_kernel(const float* __restrict__ emb) {
    int k = blockIdx.x * blockDim.x + threadIdx.x;
    if (k >= NBCODE) return;
    const float* e = emb + (size_t)k * CC;
    float s = 0.0f;
#pragma unroll 8
    for (int d = 0; d < CC; d++) s = fmaf(e[d], e[d], s);
    g_esq[k] = s;
}

// area pooling: f_rest [B,C,16,16] -> r_nc [N, C], n = (b*sn + s)*sn + t
__global__ void pool_kernel(int sn, int fct) {
    int i = blockIdx.x * blockDim.x + threadIdx.x;
    int N = BB * sn * sn;
    if (i >= N * CC) return;
    int n = i / CC, c = i % CC;
    int t = n % sn;
    int s = (n / sn) % sn;
    int b = n / (sn * sn);
    const float* base = g_frest + ((size_t)(b * CC + c)) * (JL * JL);
    float acc = 0.0f;
    for (int dj = 0; dj < fct; dj++)
        for (int dl = 0; dl < fct; dl++)
            acc += base[(s * fct + dj) * JL + (t * fct + dl)];
    g_rnc[n * CC + c] = acc * (1.0f / (float)(fct * fct));
}

// per-row squared norm, sequential fp32 (matches reference magnitude/rounding regime)
__global__ void r2_kernel(int N) {
    int n = blockIdx.x * blockDim.x + threadIdx.x;
    if (n >= N) return;
    const float* r = g_rnc + (size_t)n * CC;
    float s = 0.0f;
#pragma unroll 8
    for (int d = 0; d < CC; d++) s = fmaf(r[d], r[d], s);
    g_r2[n] = s;
}

// scoring + per-split argmin.
// Block: 64 rows x (codes_per_split) in 128-code tiles. 256 threads.
// Thread: 4 codes (k = q + 32j, interleaved -> conflict-free LDS) x 8 rows.
// Distance = round(round(r2 + e_sq) - 2*dot), matching the reference's
// |r|^2-dominated fp32 rounding; ties resolve to lowest index via u64 key.
__global__ void argmin_kernel(const float* __restrict__ emb, int N, int nsplit) {
    extern __shared__ float4 se4[];              // [TILE_CODES][33] padded
    __shared__ float4 sr4[ROWS_PB][32];
    __shared__ float  sr2[ROWS_PB];
    __shared__ float  ses[TILE_CODES];
    __shared__ unsigned long long sbest[ROWS_PB];

    int tid = threadIdx.x;
    int q = tid & 31;          // code lane
    int o = tid >> 5;          // row octet 0..7
    int rbase = o * 8;
    int row0 = blockIdx.x * ROWS_PB;

    const float4* rnc4 = (const float4*)g_rnc;
    for (int i = tid; i < ROWS_PB * 32; i += 256) {
        int r = i >> 5, d = i & 31;
        int rg = min(row0 + r, N - 1);
        sr4[r][d] = rnc4[(size_t)rg * 32 + d];
    }
    if (tid < ROWS_PB) {
        sbest[tid] = ~0ULL;
        sr2[tid] = g_r2[min(row0 + tid, N - 1)];
    }

    float bd[8]; int bi[8];
#pragma unroll
    for (int m = 0; m < 8; m++) { bd[m] = 3.4e38f; bi[m] = 0; }

    const float4* emb4 = (const float4*)emb;
    int cps = NBCODE / nsplit;
    int k0s = blockIdx.y * cps;
    int ntiles = cps / TILE_CODES;

    for (int tile = 0; tile < ntiles; tile++) {
        int k0 = k0s + tile * TILE_CODES;
        __syncthreads();
#pragma unroll
        for (int i = 0; i < 16; i++) {
            int jj = tid + i * 256;
            int r = jj >> 5, d = jj & 31;
            se4[r * 33 + d] = emb4[(size_t)(k0 + r) * 32 + d];
        }
        if (tid < TILE_CODES) ses[tid] = g_esq[k0 + tid];
        __syncthreads();

        float acc[4][8];
#pragma unroll
        for (int j = 0; j < 4; j++)
#pragma unroll
            for (int m = 0; m < 8; m++) acc[j][m] = 0.0f;

#pragma unroll 4
        for (int d = 0; d < 32; d++) {
            float4 e0 = se4[(q      ) * 33 + d];
            float4 e1 = se4[(q + 32 ) * 33 + d];
            float4 e2 = se4[(q + 64 ) * 33 + d];
            float4 e3 = se4[(q + 96 ) * 33 + d];
#pragma unroll
            for (int m = 0; m < 8; m++) {
                float4 r = sr4[rbase + m][d];
                acc[0][m] += e0.x*r.x + e0.y*r.y + e0.z*r.z + e0.w*r.w;
                acc[1][m] += e1.x*r.x + e1.y*r.y + e1.z*r.z + e1.w*r.w;
                acc[2][m] += e2.x*r.x + e2.y*r.y + e2.z*r.z + e2.w*r.w;
                acc[3][m] += e3.x*r.x + e3.y*r.y + e3.z*r.z + e3.w*r.w;
            }
        }
#pragma unroll
        for (int j = 0; j < 4; j++) {
            int k = k0 + q + 32 * j;
            float es = ses[q + 32 * j];
#pragma unroll
            for (int m = 0; m < 8; m++) {
                float t  = __fadd_rn(sr2[rbase + m], es);     // round(r2 + e_sq)
                float sc = __fsub_rn(t, 2.0f * acc[j][m]);    // round(t - 2*dot)
                if (sc < bd[m]) { bd[m] = sc; bi[m] = k; }    // k strictly ascends per thread
            }
        }
    }

#pragma unroll
    for (int m = 0; m < 8; m++) {
        unsigned u = __float_as_uint(bd[m]);
        u = (u & 0x80000000u) ? ~u : (u | 0x80000000u);
        unsigned long long key = ((unsigned long long)u << 32) | (unsigned)bi[m];
        atomicMin(&sbest[rbase + m], key);
    }
    __syncthreads();
    if (tid < ROWS_PB && row0 + tid < N)
        g_part[blockIdx.y * N + row0 + tid] = sbest[tid];
}

__global__ void argmin_reduce(int N, int nsplit) {
    int n = blockIdx.x * blockDim.x + threadIdx.x;
    if (n >= N) return;
    unsigned long long best = ~0ULL;
    for (int s = 0; s < nsplit; s++) {
        unsigned long long v = g_part[s * N + n];
        if (v < best) best = v;
    }
    int idx = (int)(best & 0xFFFFFFFFULL);
    g_idx[n] = idx;
    atomicAdd(&g_counts[idx], 1);
}

__device__ __forceinline__ float cubicw(float x) {
    const float a = -0.75f;
    float ax = fabsf(x);
    if (ax <= 1.0f) return ((a + 2.0f) * ax - (a + 3.0f)) * ax * ax + 1.0f;
    if (ax < 2.0f)  return a * (((ax - 5.0f) * ax + 8.0f) * ax - 4.0f);
    return 0.0f;
}

// gather + bicubic upsample to [B,C,16,16] (sn < 16 path)
__global__ void upsample_kernel(const float* __restrict__ emb, int sn) {
    int i = blockIdx.x * blockDim.x + threadIdx.x;
    if (i >= FHN) return;
    int l = i & 15;
    int j = (i >> 4) & 15;
    int c = (i >> 8) & 127;
    int b = i >> 15;
    float scale = (float)sn / 16.0f;
    float xj = (j + 0.5f) * scale - 0.5f;
    int x0j = (int)floorf(xj);
    float tj = xj - (float)x0j;
    float xl = (l + 0.5f) * scale - 0.5f;
    int x0l = (int)floorf(xl);
    float tl = xl - (float)x0l;

    float acc = 0.0f;
#pragma unroll
    for (int kj = 0; kj < 4; kj++) {
        float wj = cubicw(tj + 1.0f - (float)kj);
        int sj = min(max(x0j - 1 + kj, 0), sn - 1);
#pragma unroll
        for (int kl = 0; kl < 4; kl++) {
            float wl = cubicw(tl + 1.0f - (float)kl);
            int sl = min(max(x0l - 1 + kl, 0), sn - 1);
            int n = (b * sn + sj) * sn + sl;
            acc += wj * wl * emb[(size_t)g_idx[n] * CC + c];
        }
    }
    g_hs[i] = acc;
}

// sn == 16: bicubic is the identity -> coalesced gather + transpose.
// Block = (b, 32-pixel tile). Warps read full emb rows (512B), write 128B runs.
__global__ void gather16_kernel(const float* __restrict__ emb) {
    __shared__ float s[32 * 133];
    int tid = threadIdx.x;
    int lane = tid & 31, w = tid >> 5;          // 8 warps
    int b  = blockIdx.x >> 3;
    int n0 = (blockIdx.x & 7) * 32;

    const float4* emb4 = (const float4*)emb;
#pragma unroll
    for (int st = 0; st < 4; st++) {
        int i = w * 4 + st;                      // local pixel 0..31
        int idx = g_idx[b * 256 + n0 + i];
        float4 v = emb4[(size_t)idx * 32 + lane];
        s[i * 133 + lane * 4 + 0] = v.x;
        s[i * 133 + lane * 4 + 1] = v.y;
        s[i * 133 + lane * 4 + 2] = v.z;
        s[i * 133 + lane * 4 + 3] = v.w;
    }
    __syncthreads();
#pragma unroll
    for (int it = 0; it < 16; it++) {
        int c = w + it * 8;
        g_hs[(((size_t)b * 128 + c) << 8) + n0 + lane] = s[lane * 133 + c];
    }
}

// conv3x3 (SAME) + bias, phi blend (0.5/0.5), f_hat/f_rest update, loss.
// Double-buffered plane/weights: 1 barrier per ci, LDG prefetch overlapped.
__global__ void conv_phi_kernel(const float* __restrict__ w, const float* __restrict__ bias,
                                const float* __restrict__ f_in, float* __restrict__ fhat) {
    __shared__ float plane[2][256];
    __shared__ float wsh[2][144];
    __shared__ float red[256];

    int b    = blockIdx.x >> 3;
    int cog  = blockIdx.x & 7;
    int cbase = cog * 16;
    int tid  = threadIdx.x;
    int j = tid >> 4, l = tid & 15;
    int co9 = tid / 9, q9 = tid % 9;

    float acc[16];
#pragma unroll
    for (int co = 0; co < 16; co++) acc[co] = bias[cbase + co];

    const float* hsb = g_hs + (((size_t)b * CC) << 8);

    float v = hsb[tid];
    float wv = 0.0f;
    if (tid < 144) wv = w[((size_t)(cbase + co9) * CC + 0) * 9 + q9];

    for (int ci = 0; ci < CC; ci++) {
        int buf = ci & 1;
        plane[buf][tid] = v;
        if (tid < 144) wsh[buf][tid] = wv;
        if (ci < CC - 1) {
            v = hsb[((ci + 1) << 8) + tid];
            if (tid < 144) wv = w[((size_t)(cbase + co9) * CC + (ci + 1)) * 9 + q9];
        }
        __syncthreads();
        float vv[9];
#pragma unroll
        for (int dj = 0; dj < 3; dj++)
#pragma unroll
            for (int dl = 0; dl < 3; dl++) {
                int jj = j + dj - 1, ll = l + dl - 1;
                vv[dj * 3 + dl] = (jj >= 0 && jj < 16 && ll >= 0 && ll < 16)
                                  ? plane[buf][(jj << 4) + ll] : 0.0f;
            }
#pragma unroll
        for (int co = 0; co < 16; co++) {
            float s = 0.0f;
#pragma unroll
            for (int qq = 0; qq < 9; qq++) s += wsh[buf][co * 9 + qq] * vv[qq];
            acc[co] += s;
        }
    }

    float lsum = 0.0f;
#pragma unroll
    for (int co = 0; co < 16; co++) {
        size_t gi = ((size_t)(b * CC + cbase + co) << 8) + tid;
        float h = 0.5f * g_hs[gi] + 0.5f * acc[co];
        float fh = fhat[gi] + h;
        fhat[gi] = fh;
        g_frest[gi] -= h;
        float d = fh - f_in[gi];
        lsum += d * d;
    }
    red[tid] = lsum;
    __syncthreads();
    for (int s = 128; s > 0; s >>= 1) {
        if (tid < s) red[tid] += red[tid + s];
        __syncthreads();
    }
    // loss = (1+beta)/SN * sum(mse) = 0.25 * sum(sum_sq)/FHN
    if (tid == 0) atomicAdd(&g_loss, red[0] * (0.25f / (float)FHN));
}

__global__ void final_kernel(float* __restrict__ out) {
    __shared__ float red[256];
    int tid = threadIdx.x;
    float s = 0.0f;
    for (int k = tid; k < NBCODE; k += 256) {
        float p = (float)g_counts[k] * (1.0f / (float)NTOT);
        s += p * logf(p + 1e-10f);
    }
    red[tid] = s;
    __syncthreads();
    for (int st = 128; st > 0; st >>= 1) {
        if (tid < st) red[tid] += red[tid + st];
        __syncthreads();
    }
    if (tid == 0) {
        out[FHN]     = g_loss;
        out[FHN + 1] = expf(-red[0]);
    }
}

// ------------------------------------------------------------------
extern "C" void kernel_launch(void* const* d_in, const int* in_sizes, int n_in,
                              void* d_out, int out_size) {
    const float* f     = (const float*)d_in[0];   // [16,128,16,16]
    const float* emb   = (const float*)d_in[1];   // [16384,128]
    const float* phi_w = (const float*)d_in[2];   // [4,128,128,3,3]
    const float* phi_b = (const float*)d_in[3];   // [4,128]
    float* out = (float*)d_out;                   // [524288 fhat | loss | perplexity]

    cudaFuncSetAttribute(argmin_kernel,
                         cudaFuncAttributeMaxDynamicSharedMemorySize, ARGMIN_DYN_SMEM);

    init_kernel<<<(FHN + 255) / 256, 256>>>(f, out);
    esq_kernel<<<NBCODE / 256, 256>>>(emb);

    const int sns[5]    = {1, 2, 4, 8, 16};
    const int phis[5]   = {0, 1, 1, 2, 3};
    const int splits[5] = {128, 128, 64, 32, 8};
    for (int si = 0; si < 5; si++) {
        int sn = sns[si];
        int N = BB * sn * sn;
        int fct = 16 / sn;
        int nsplit = splits[si];
        pool_kernel<<<(N * CC + 255) / 256, 256>>>(sn, fct);
        r2_kernel<<<(N + 255) / 256, 256>>>(N);
        dim3 g((N + ROWS_PB - 1) / ROWS_PB, nsplit);
        argmin_kernel<<<g, 256, ARGMIN_DYN_SMEM>>>(emb, N, nsplit);
        argmin_reduce<<<(N + 255) / 256, 256>>>(N, nsplit);
        if (sn == 16) {
            gather16_kernel<<<128, 256>>>(emb);
        } else {
            upsample_kernel<<<FHN / 256, 256>>>(emb, sn);
        }
        int k = phis[si];
        conv_phi_kernel<<<128, 256>>>(phi_w + (size_t)k * CC * CC * 9,
                                      phi_b + (size_t)k * CC, f, out);
    }
    final_kernel<<<1, 256>>>(out);
}

// round 6
// speedup vs baseline: 13.0914x; 1.5460x over previous
#include <cuda_runtime.h>
#include <cuda_bf16.h>
#include <math.h>

#define BB 16
#define CC 128
#define NBCODE 16384
#define NTOT 5456
#define FHN (BB*CC*16*16)   // 524288
#define CAP (1<<18)
#define CO_SMEM ((256*68 + 128*68)*4)   // 104448 bytes

// ---- device scratch (no allocations allowed) ----
__device__ float g_frest[FHN];
__device__ float g_rnc[4096*CC];
__device__ float g_r2[4096];
__device__ float g_eps[4096];
__device__ float g_hs[FHN];
__device__ unsigned g_cmin[4096];
__device__ unsigned long long g_best[4096];
__device__ unsigned g_cand[CAP];
__device__ int g_ccnt;
__device__ int g_idx[4096];
__device__ int g_counts[NBCODE];
__device__ float g_loss;
__device__ float g_esq[NBCODE];
__device__ int g_esqmax;
__device__ unsigned g_embw[NBCODE*64];   // bf16x2 words [code][64]

// ------------------------------------------------------------------
__device__ __forceinline__ void mma16816(float* d, const unsigned* a, unsigned b0, unsigned b1) {
    asm volatile("mma.sync.aligned.m16n8k16.row.col.f32.bf16.bf16.f32 "
                 "{%0,%1,%2,%3}, {%4,%5,%6,%7}, {%8,%9}, {%0,%1,%2,%3};"
                 : "+f"(d[0]), "+f"(d[1]), "+f"(d[2]), "+f"(d[3])
                 : "r"(a[0]), "r"(a[1]), "r"(a[2]), "r"(a[3]), "r"(b0), "r"(b1));
}
// shared coarse-score: identical rounding in pass1/pass2 (no re-association)
__device__ __forceinline__ float csc(float r2, float es, float v) {
    return __fmaf_rn(-2.0f, v, __fadd_rn(r2, es));
}
__device__ __forceinline__ unsigned fkey(float f) {
    unsigned u = __float_as_uint(f);
    return (u & 0x80000000u) ? ~u : (u | 0x80000000u);
}

// ------------------------------------------------------------------
__global__ void init_kernel(const float* __restrict__ f, float* __restrict__ fhat) {
    int i = blockIdx.x * blockDim.x + threadIdx.x;
    if (i < FHN) { fhat[i] = 0.0f; g_frest[i] = f[i]; }
    if (i < NBCODE) g_counts[i] = 0;
    if (i == 0) { g_loss = 0.0f; g_esqmax = 0; }
}

__global__ void esq_kernel(const float* __restrict__ emb) {
    int k = blockIdx.x * blockDim.x + threadIdx.x;
    if (k >= NBCODE) return;
    const float* e = emb + (size_t)k * CC;
    float s = 0.0f;
#pragma unroll 8
    for (int d = 0; d < CC; d++) s = fmaf(e[d], e[d], s);
    g_esq[k] = s;
    atomicMax(&g_esqmax, __float_as_int(s));   // s >= 0: int order == float order
}

__global__ void pack_emb(const float* __restrict__ emb) {
    int i = blockIdx.x * 256 + threadIdx.x;    // NBCODE*64 words
    float2 v = ((const float2*)emb)[i];
    __nv_bfloat162 p = __floats2bfloat162_rn(v.x, v.y);
    g_embw[i] = *(unsigned*)&p;
}

// area pooling: f_rest [B,C,16,16] -> r_nc [N, C]
__global__ void pool_kernel(int sn, int fct) {
    int i = blockIdx.x * blockDim.x + threadIdx.x;
    int N = BB * sn * sn;
    if (i >= N * CC) return;
    int n = i / CC, c = i % CC;
    int t = n % sn;
    int s = (n / sn) % sn;
    int b = n / (sn * sn);
    const float* base = g_frest + ((size_t)(b * CC + c)) * 256;
    float acc = 0.0f;
    for (int dj = 0; dj < fct; dj++)
        for (int dl = 0; dl < fct; dl++)
            acc += base[(s * fct + dj) * 16 + (t * fct + dl)];
    g_rnc[n * CC + c] = acc * (1.0f / (float)(fct * fct));
}

// per-row squared norm + per-scale state init
__global__ void r2_kernel(int N) {
    int n = blockIdx.x * blockDim.x + threadIdx.x;
    if (n == 0) g_ccnt = 0;
    if (n >= N) return;
    const float* r = g_rnc + (size_t)n * CC;
    float s = 0.0f;
#pragma unroll 8
    for (int d = 0; d < CC; d++) s = fmaf(r[d], r[d], s);
    g_r2[n] = s;
    float emax = __int_as_float(g_esqmax);
    g_eps[n] = 0.0203f * sqrtf(s * emax) + 4e-4f;   // worst-case bf16 coarse error bound
    g_cmin[n] = 0xFFFFFFFFu;
    g_best[n] = ~0ULL;
}

// ------------------------------------------------------------------
// Coarse bf16 HMMA scoring. Block: 256 thr (8 warps), 256 rows, cpb codes.
// Warp owns 32 rows (A frags in regs); codes streamed via 128-code smem chunks.
// pass=0: per-row coarse min -> g_cmin. pass=1: append all (row,code) with
// sc <= cmin + eps_row to candidate list (winner capture is deterministic).
__global__ __launch_bounds__(256, 1)
void coarse_kernel(int N, int nsplit, int pass) {
    extern __shared__ unsigned sm[];
    unsigned* sA = sm;              // [256][68]
    unsigned* sB = sm + 256 * 68;   // [128][68]
    int tid = threadIdx.x, lane = tid & 31, wid = tid >> 5;
    int g = lane >> 2, t = lane & 3;
    int row0 = blockIdx.x * 256;

    const float4* rnc4 = (const float4*)g_rnc;
    for (int i = tid; i < 256 * 32; i += 256) {
        int r = i >> 5, q = i & 31;
        int rg = min(row0 + r, N - 1);
        float4 v = rnc4[(size_t)rg * 32 + q];
        __nv_bfloat162 p0 = __floats2bfloat162_rn(v.x, v.y);
        __nv_bfloat162 p1 = __floats2bfloat162_rn(v.z, v.w);
        sA[r * 68 + 2 * q]     = *(unsigned*)&p0;
        sA[r * 68 + 2 * q + 1] = *(unsigned*)&p1;
    }
    __syncthreads();

    unsigned a[2][8][4];
    int rl0 = wid * 32;
#pragma unroll
    for (int tile = 0; tile < 2; tile++) {
        int rb = rl0 + tile * 16;
#pragma unroll
        for (int ks = 0; ks < 8; ks++) {
            a[tile][ks][0] = sA[(rb + g    ) * 68 + ks * 8 + t];
            a[tile][ks][1] = sA[(rb + g + 8) * 68 + ks * 8 + t];
            a[tile][ks][2] = sA[(rb + g    ) * 68 + ks * 8 + t + 4];
            a[tile][ks][3] = sA[(rb + g + 8) * 68 + ks * 8 + t + 4];
        }
    }

    int rows[4]; float r2s[4], thr[4], lmin[4];
#pragma unroll
    for (int s = 0; s < 4; s++) {
        int tile = s >> 1, half = s & 1;
        rows[s] = row0 + rl0 + tile * 16 + g + half * 8;
        int rc = min(rows[s], N - 1);
        r2s[s] = g_r2[rc];
        lmin[s] = 3.4e38f;
        thr[s] = 0.0f;
        if (pass) {
            unsigned u = g_cmin[rc];
            float cm = (u & 0x80000000u) ? __uint_as_float(u & 0x7FFFFFFFu)
                                         : __uint_as_float(~u);
            thr[s] = cm + g_eps[rc];
        }
    }

    int cpb = NBCODE / nsplit;
    int c0s = blockIdx.y * cpb;
    const uint4* embw4 = (const uint4*)g_embw;

    for (int chunk = 0; chunk < cpb / 128; chunk++) {
        int c0 = c0s + chunk * 128;
        __syncthreads();
        for (int i = tid; i < 128 * 16; i += 256) {
            int r = i >> 4, q = i & 15;
            uint4 v = embw4[(size_t)(c0 + r) * 16 + q];
            sB[r * 68 + 4 * q]     = v.x;
            sB[r * 68 + 4 * q + 1] = v.y;
            sB[r * 68 + 4 * q + 2] = v.z;
            sB[r * 68 + 4 * q + 3] = v.w;
        }
        __syncthreads();
#pragma unroll 1
        for (int grp = 0; grp < 16; grp++) {
            float d0[4] = {0, 0, 0, 0}, d1[4] = {0, 0, 0, 0};
            const unsigned* brow = sB + (grp * 8 + g) * 68;
#pragma unroll
            for (int ks = 0; ks < 8; ks++) {
                unsigned b0 = brow[ks * 8 + t], b1 = brow[ks * 8 + t + 4];
                mma16816(d0, a[0][ks], b0, b1);
                mma16816(d1, a[1][ks], b0, b1);
            }
            int cc = c0 + grp * 8 + 2 * t;
            float e0 = __ldg(&g_esq[cc]), e1 = __ldg(&g_esq[cc + 1]);
            float vs[4][2] = {{d0[0], d0[1]}, {d0[2], d0[3]},
                              {d1[0], d1[1]}, {d1[2], d1[3]}};
            if (!pass) {
#pragma unroll
                for (int s = 0; s < 4; s++) {
                    float s0 = csc(r2s[s], e0, vs[s][0]);
                    float s1 = csc(r2s[s], e1, vs[s][1]);
                    lmin[s] = fminf(lmin[s], fminf(s0, s1));
                }
            } else {
#pragma unroll
                for (int s = 0; s < 4; s++) {
                    float s0 = csc(r2s[s], e0, vs[s][0]);
                    float s1 = csc(r2s[s], e1, vs[s][1]);
                    if (rows[s] < N) {
                        if (s0 <= thr[s]) {
                            int p = atomicAdd(&g_ccnt, 1);
                            if (p < CAP) g_cand[p] = ((unsigned)rows[s] << 14) | (unsigned)cc;
                        }
                        if (s1 <= thr[s]) {
                            int p = atomicAdd(&g_ccnt, 1);
                            if (p < CAP) g_cand[p] = ((unsigned)rows[s] << 14) | (unsigned)(cc + 1);
                        }
                    }
                }
            }
        }
    }
    if (!pass) {
#pragma unroll
        for (int s = 0; s < 4; s++)
            if (rows[s] < N) atomicMin(&g_cmin[rows[s]], fkey(lmin[s]));
    }
}

// exact fp32 rescore of candidates; same rounding emulation + tie-break as R2.
__global__ void refine_kernel(const float* __restrict__ emb) {
    int wg = (blockIdx.x * blockDim.x + threadIdx.x) >> 5;
    int lane = threadIdx.x & 31;
    int cnt = min(g_ccnt, CAP);
    int nw = (gridDim.x * blockDim.x) >> 5;
    const float4* rnc4 = (const float4*)g_rnc;
    const float4* emb4 = (const float4*)emb;
    for (int ci = wg; ci < cnt; ci += nw) {
        unsigned e = g_cand[ci];
        int row = e >> 14, code = e & 16383;
        float4 r = rnc4[(size_t)row * 32 + lane];
        float4 c = emb4[(size_t)code * 32 + lane];
        float dot = r.x * c.x + r.y * c.y + r.z * c.z + r.w * c.w;
#pragma unroll
        for (int o = 16; o > 0; o >>= 1) dot += __shfl_xor_sync(0xFFFFFFFFu, dot, o);
        if (lane == 0) {
            float tt = __fadd_rn(g_r2[row], g_esq[code]);   // round(r2 + e_sq)
            float sc = __fsub_rn(tt, 2.0f * dot);           // round(t - 2*dot)
            unsigned long long key = ((unsigned long long)fkey(sc) << 32) | (unsigned)code;
            atomicMin(&g_best[row], key);
        }
    }
}

__global__ void fill_idx(int N) {
    int n = blockIdx.x * blockDim.x + threadIdx.x;
    if (n >= N) return;
    int idx = (int)(unsigned)(g_best[n] & 0xFFFFFFFFull);
    g_idx[n] = idx;
    atomicAdd(&g_counts[idx], 1);
}

// ------------------------------------------------------------------
__device__ __forceinline__ float cubicw(float x) {
    const float a = -0.75f;
    float ax = fabsf(x);
    if (ax <= 1.0f) return ((a + 2.0f) * ax - (a + 3.0f)) * ax * ax + 1.0f;
    if (ax < 2.0f)  return a * (((ax - 5.0f) * ax + 8.0f) * ax - 4.0f);
    return 0.0f;
}

__global__ void upsample_kernel(const float* __restrict__ emb, int sn) {
    int i = blockIdx.x * blockDim.x + threadIdx.x;
    if (i >= FHN) return;
    int l = i & 15;
    int j = (i >> 4) & 15;
    int c = (i >> 8) & 127;
    int b = i >> 15;
    float scale = (float)sn / 16.0f;
    float xj = (j + 0.5f) * scale - 0.5f;
    int x0j = (int)floorf(xj);
    float tj = xj - (float)x0j;
    float xl = (l + 0.5f) * scale - 0.5f;
    int x0l = (int)floorf(xl);
    float tl = xl - (float)x0l;

    float acc = 0.0f;
#pragma unroll
    for (int kj = 0; kj < 4; kj++) {
        float wj = cubicw(tj + 1.0f - (float)kj);
        int sj = min(max(x0j - 1 + kj, 0), sn - 1);
#pragma unroll
        for (int kl = 0; kl < 4; kl++) {
            float wl = cubicw(tl + 1.0f - (float)kl);
            int sl = min(max(x0l - 1 + kl, 0), sn - 1);
            int n = (b * sn + sj) * sn + sl;
            acc += wj * wl * emb[(size_t)g_idx[n] * CC + c];
        }
    }
    g_hs[i] = acc;
}

__global__ void gather16_kernel(const float* __restrict__ emb) {
    __shared__ float s[32 * 133];
    int tid = threadIdx.x;
    int lane = tid & 31, w = tid >> 5;
    int b  = blockIdx.x >> 3;
    int n0 = (blockIdx.x & 7) * 32;

    const float4* emb4 = (const float4*)emb;
#pragma unroll
    for (int st = 0; st < 4; st++) {
        int i = w * 4 + st;
        int idx = g_idx[b * 256 + n0 + i];
        float4 v = emb4[(size_t)idx * 32 + lane];
        s[i * 133 + lane * 4 + 0] = v.x;
        s[i * 133 + lane * 4 + 1] = v.y;
        s[i * 133 + lane * 4 + 2] = v.z;
        s[i * 133 + lane * 4 + 3] = v.w;
    }
    __syncthreads();
#pragma unroll
    for (int it = 0; it < 16; it++) {
        int c = w + it * 8;
        g_hs[(((size_t)b * 128 + c) << 8) + n0 + lane] = s[lane * 133 + c];
    }
}

__global__ void conv_phi_kernel(const float* __restrict__ w, const float* __restrict__ bias,
                                const float* __restrict__ f_in, float* __restrict__ fhat) {
    __shared__ float plane[2][256];
    __shared__ float wsh[2][144];
    __shared__ float red[256];

    int b    = blockIdx.x >> 3;
    int cog  = blockIdx.x & 7;
    int cbase = cog * 16;
    int tid  = threadIdx.x;
    int j = tid >> 4, l = tid & 15;
    int co9 = tid / 9, q9 = tid % 9;

    float acc[16];
#pragma unroll
    for (int co = 0; co < 16; co++) acc[co] = bias[cbase + co];

    const float* hsb = g_hs + (((size_t)b * CC) << 8);

    float v = hsb[tid];
    float wv = 0.0f;
    if (tid < 144) wv = w[((size_t)(cbase + co9) * CC + 0) * 9 + q9];

    for (int ci = 0; ci < CC; ci++) {
        int buf = ci & 1;
        plane[buf][tid] = v;
        if (tid < 144) wsh[buf][tid] = wv;
        if (ci < CC - 1) {
            v = hsb[((ci + 1) << 8) + tid];
            if (tid < 144) wv = w[((size_t)(cbase + co9) * CC + (ci + 1)) * 9 + q9];
        }
        __syncthreads();
        float vv[9];
#pragma unroll
        for (int dj = 0; dj < 3; dj++)
#pragma unroll
            for (int dl = 0; dl < 3; dl++) {
                int jj = j + dj - 1, ll = l + dl - 1;
                vv[dj * 3 + dl] = (jj >= 0 && jj < 16 && ll >= 0 && ll < 16)
                                  ? plane[buf][(jj << 4) + ll] : 0.0f;
            }
#pragma unroll
        for (int co = 0; co < 16; co++) {
            float s = 0.0f;
#pragma unroll
            for (int qq = 0; qq < 9; qq++) s += wsh[buf][co * 9 + qq] * vv[qq];
            acc[co] += s;
        }
    }

    float lsum = 0.0f;
#pragma unroll
    for (int co = 0; co < 16; co++) {
        size_t gi = ((size_t)(b * CC + cbase + co) << 8) + tid;
        float h = 0.5f * g_hs[gi] + 0.5f * acc[co];
        float fh = fhat[gi] + h;
        fhat[gi] = fh;
        g_frest[gi] -= h;
        float d = fh - f_in[gi];
        lsum += d * d;
    }
    red[tid] = lsum;
    __syncthreads();
    for (int s = 128; s > 0; s >>= 1) {
        if (tid < s) red[tid] += red[tid + s];
        __syncthreads();
    }
    if (tid == 0) atomicAdd(&g_loss, red[0] * (0.25f / (float)FHN));
}

__global__ void final_kernel(float* __restrict__ out) {
    __shared__ float red[256];
    int tid = threadIdx.x;
    float s = 0.0f;
    for (int k = tid; k < NBCODE; k += 256) {
        float p = (float)g_counts[k] * (1.0f / (float)NTOT);
        s += p * logf(p + 1e-10f);
    }
    red[tid] = s;
    __syncthreads();
    for (int st = 128; st > 0; st >>= 1) {
        if (tid < st) red[tid] += red[tid + st];
        __syncthreads();
    }
    if (tid == 0) {
        out[FHN]     = g_loss;
        out[FHN + 1] = expf(-red[0]);
    }
}

// ------------------------------------------------------------------
extern "C" void kernel_launch(void* const* d_in, const int* in_sizes, int n_in,
                              void* d_out, int out_size) {
    const float* f     = (const float*)d_in[0];
    const float* emb   = (const float*)d_in[1];
    const float* phi_w = (const float*)d_in[2];
    const float* phi_b = (const float*)d_in[3];
    float* out = (float*)d_out;

    cudaFuncSetAttribute(coarse_kernel, cudaFuncAttributeMaxDynamicSharedMemorySize, CO_SMEM);

    init_kernel<<<(FHN + 255) / 256, 256>>>(f, out);
    esq_kernel<<<NBCODE / 256, 256>>>(emb);
    pack_emb<<<NBCODE * 64 / 256, 256>>>(emb);

    const int sns[5]    = {1, 2, 4, 8, 16};
    const int phis[5]   = {0, 1, 1, 2, 3};
    const int splits[5] = {64, 64, 64, 32, 16};
    for (int si = 0; si < 5; si++) {
        int sn = sns[si];
        int N = BB * sn * sn;
        int fct = 16 / sn;
        int nsplit = splits[si];
        pool_kernel<<<(N * CC + 255) / 256, 256>>>(sn, fct);
        r2_kernel<<<(N + 255) / 256, 256>>>(N);
        dim3 g((N + 255) / 256, nsplit);
        coarse_kernel<<<g, 256, CO_SMEM>>>(N, nsplit, 0);
        coarse_kernel<<<g, 256, CO_SMEM>>>(N, nsplit, 1);
        refine_kernel<<<128, 256>>>(emb);
        fill_idx<<<(N + 255) / 256, 256>>>(N);
        if (sn == 16) {
            gather16_kernel<<<128, 256>>>(emb);
        } else {
            upsample_kernel<<<FHN / 256, 256>>>(emb, sn);
        }
        int k = phis[si];
        conv_phi_kernel<<<128, 256>>>(phi_w + (size_t)k * CC * CC * 9,
                                      phi_b + (size_t)k * CC, f, out);
    }
    final_kernel<<<1, 256>>>(out);
}